// round 6
// baseline (speedup 1.0000x reference)
#include <cuda_runtime.h>
#include <math.h>
#include <stdint.h>

#define NNODE 512
#define MEMD  512
#define NIOU  1536
#define NCOMB 2048
#define NPAD  513   // row 512 = permanent zero (padded child)

// Scratch state (device globals: allocation-free rule)
__device__ float g_xiouf[2 * NNODE * NCOMB];  // [xiou(1536) | xf(512)] per node, biases included
__device__ float g_ziou[2 * NNODE * NIOU];    // (sum_children h) @ W_iouh, internal nodes (j>=384) only
__device__ float g_y[2 * NPAD * MEMD];        // h @ W_fh per node (+ pad zero row)
__device__ float g_c[2 * NPAD * MEMD];
__device__ float g_h[2 * NPAD * MEMD];
__device__ float g_part[16 * MEMD];           // head partial sums

__device__ __forceinline__ float sigm(float x) { return 1.f / (1.f + __expf(-x)); }
__device__ __forceinline__ float4 ld4(const float* p) { return *(const float4*)p; }
__device__ __forceinline__ float4 f4add(float4 a, float4 b) {
    return make_float4(a.x + b.x, a.y + b.y, a.z + b.z, a.w + b.w);
}
__device__ __forceinline__ uint32_t to_tf32(float x) {
    uint32_t r; asm("cvt.rna.tf32.f32 %0, %1;" : "=r"(r) : "f"(x)); return r;
}
__device__ __forceinline__ uint4 cvt4(float4 v) {
    uint4 r; r.x = to_tf32(v.x); r.y = to_tf32(v.y); r.z = to_tf32(v.z); r.w = to_tf32(v.w);
    return r;
}
__device__ __forceinline__ void mma_tf32(float d[4], const uint32_t a[4], const uint32_t b[2]) {
    asm volatile(
        "mma.sync.aligned.m16n8k8.row.col.f32.tf32.tf32.f32 "
        "{%0,%1,%2,%3}, {%4,%5,%6,%7}, {%8,%9}, {%0,%1,%2,%3};"
        : "+f"(d[0]), "+f"(d[1]), "+f"(d[2]), "+f"(d[3])
        : "r"(a[0]), "r"(a[1]), "r"(a[2]), "r"(a[3]), "r"(b[0]), "r"(b[1]));
}

// Zero the permanent pad rows (deterministic every call).
__global__ void k_zero() {
    int tid = threadIdx.x;  // 0..511
#pragma unroll
    for (int t = 0; t < 2; t++) {
        g_y[(size_t)(t * NPAD + NNODE) * MEMD + tid] = 0.f;
        g_c[(size_t)(t * NPAD + NNODE) * MEMD + tid] = 0.f;
        g_h[(size_t)(t * NPAD + NNODE) * MEMD + tid] = 0.f;
    }
}

// Precompute tf32 GEMM: 32(M)x64(N) block tile, BK=32, 256 threads (8 warps,
// 16x16 warp tiles), double-buffered smem, conflict-free strides (40/72 = 8 mod 32).
// C[m] = emb[tok[m]] @ [W_ioux|W_fx] + [b_ioux|b_fx]  -> g_xiouf  (m over 1024 rows)
__global__ __launch_bounds__(256) void k_pre(
    const float* __restrict__ emb, const int* __restrict__ linp, const int* __restrict__ rinp,
    const float* __restrict__ W0, const float* __restrict__ W1,
    const float* __restrict__ b0, const float* __restrict__ b1)
{
    __shared__ uint32_t As[2][32][40];
    __shared__ uint32_t Bs[2][32][72];

    const int tid = threadIdx.x;
    const int n0 = blockIdx.x * 64;
    const int m0 = blockIdx.y * 32;

    const int arow = tid >> 3;
    const int acol = (tid & 7) << 2;
    const int brow = tid >> 4;
    const int bc4  = (tid & 15) << 2;

    const float* aptr;
    {
        int gm = m0 + arow;
        int tok = (gm < NNODE) ? linp[gm] : rinp[gm - NNODE];
        aptr = emb + (size_t)tok * MEMD + acol;
    }

    const float* Bsrc; int bld; const float* bias;
    if (n0 < NIOU) { Bsrc = W0 + n0;          bld = NIOU; bias = b0 + n0; }
    else           { Bsrc = W1 + (n0 - NIOU); bld = MEMD; bias = b1 + n0 - NIOU; }

    const int lane = tid & 31, wid = tid >> 5;
    const int wm = (wid & 1) * 16, wn = (wid >> 1) * 16;
    const int g = lane >> 2, tg = lane & 3;

    float acc[2][4] = {};

    *(uint4*)&As[0][arow][acol]     = cvt4(ld4(aptr));
    *(uint4*)&Bs[0][brow][bc4]      = cvt4(ld4(Bsrc + (size_t)brow * bld + bc4));
    *(uint4*)&Bs[0][brow + 16][bc4] = cvt4(ld4(Bsrc + (size_t)(brow + 16) * bld + bc4));
    __syncthreads();

    int cur = 0;
    for (int it = 0; it < 16; it++) {
        float4 an, bn0, bn1;
        if (it < 15) {
            int k0 = (it + 1) * 32;
            an  = ld4(aptr + k0);
            bn0 = ld4(Bsrc + (size_t)(k0 + brow) * bld + bc4);
            bn1 = ld4(Bsrc + (size_t)(k0 + brow + 16) * bld + bc4);
        }
#pragma unroll
        for (int kk = 0; kk < 32; kk += 8) {
            uint32_t af[4], bf[2][2];
            af[0] = As[cur][wm + g][kk + tg];
            af[1] = As[cur][wm + g + 8][kk + tg];
            af[2] = As[cur][wm + g][kk + tg + 4];
            af[3] = As[cur][wm + g + 8][kk + tg + 4];
#pragma unroll
            for (int j = 0; j < 2; j++) {
                int bc = wn + j * 8 + g;
                bf[j][0] = Bs[cur][kk + tg][bc];
                bf[j][1] = Bs[cur][kk + tg + 4][bc];
            }
            mma_tf32(acc[0], af, bf[0]);
            mma_tf32(acc[1], af, bf[1]);
        }
        if (it < 15) {
            int nxt = cur ^ 1;
            *(uint4*)&As[nxt][arow][acol]     = cvt4(an);
            *(uint4*)&Bs[nxt][brow][bc4]      = cvt4(bn0);
            *(uint4*)&Bs[nxt][brow + 16][bc4] = cvt4(bn1);
            __syncthreads();
            cur = nxt;
        }
    }

#pragma unroll
    for (int j = 0; j < 2; j++) {
        int colin = wn + j * 8 + 2 * tg;
#pragma unroll
        for (int r = 0; r < 2; r++) {
            int mrow = m0 + wm + g + r * 8;
            float2 v = make_float2(acc[j][2 * r], acc[j][2 * r + 1]);
            v.x += bias[colin]; v.y += bias[colin + 1];
            *(float2*)(g_xiouf + (size_t)mrow * NCOMB + n0 + colin) = v;
        }
    }
}

// Level GEMM, two fused sub-GEMMs per launch (linearized blockIdx.x):
//   f-part   (blocks [0, 8*mtf)):        g_y[j]    = g_h[j] @ W_fh           (rows j0f..j0f+Pf)
//   iou-part (blocks [8*mtf, +24*mti)):  g_ziou[j] = (sum_ch g_h[ch]) @ W_iouh (rows j0i..j0i+Pi)
__global__ __launch_bounds__(256) void k_lvl(
    const int* __restrict__ lch, const int* __restrict__ rch,
    const float* __restrict__ Wiouh, const float* __restrict__ Wfh,
    int j0f, int Pf, int j0i, int Pi, int mtf)
{
    __shared__ uint32_t As[2][32][40];
    __shared__ uint32_t Bs[2][32][72];

    const int tid = threadIdx.x;
    const int t = blockIdx.z;
    const int bx = blockIdx.x;
    const bool fpart = (bx < 8 * mtf);

    int n0, mtile;
    const float* Bsrc; int bld;
    if (fpart) { n0 = (bx & 7) * 64; mtile = bx >> 3; Bsrc = Wfh + n0; bld = MEMD; }
    else {
        int b2 = bx - 8 * mtf;
        n0 = (b2 % 24) * 64; mtile = b2 / 24; Bsrc = Wiouh + n0; bld = NIOU;
    }

    const int arow = tid >> 3;
    const int acol = (tid & 7) << 2;
    const int brow = tid >> 4;
    const int bc4  = (tid & 15) << 2;

    const int gm = mtile * 32 + arow;
    const int Plim = fpart ? Pf : Pi;
    const bool avalid = (gm < Plim);
    const float *ap0, *ap1 = 0, *ap2 = 0, *ap3 = 0;
    if (fpart) {
        ap0 = g_h + (size_t)(t * NPAD + j0f + (avalid ? gm : 0)) * MEMD + acol;
    } else {
        int j = j0i + (avalid ? gm : 0);
        const int* ch = (t ? rch : lch) + j * 4;
        ap0 = g_h + (size_t)(t * NPAD + ch[0]) * MEMD + acol;
        ap1 = g_h + (size_t)(t * NPAD + ch[1]) * MEMD + acol;
        ap2 = g_h + (size_t)(t * NPAD + ch[2]) * MEMD + acol;
        ap3 = g_h + (size_t)(t * NPAD + ch[3]) * MEMD + acol;
    }

    const int lane = tid & 31, wid = tid >> 5;
    const int wm = (wid & 1) * 16, wn = (wid >> 1) * 16;
    const int g = lane >> 2, tg = lane & 3;

    float acc[2][4] = {};

    // prologue
    {
        float4 av = make_float4(0.f, 0.f, 0.f, 0.f);
        if (avalid) {
            av = ld4(ap0);
            if (!fpart) av = f4add(f4add(av, ld4(ap1)), f4add(ld4(ap2), ld4(ap3)));
        }
        *(uint4*)&As[0][arow][acol]     = cvt4(av);
        *(uint4*)&Bs[0][brow][bc4]      = cvt4(ld4(Bsrc + (size_t)brow * bld + bc4));
        *(uint4*)&Bs[0][brow + 16][bc4] = cvt4(ld4(Bsrc + (size_t)(brow + 16) * bld + bc4));
    }
    __syncthreads();

    int cur = 0;
    for (int it = 0; it < 16; it++) {
        float4 an = make_float4(0.f, 0.f, 0.f, 0.f), bn0, bn1;
        if (it < 15) {
            int k0 = (it + 1) * 32;
            if (avalid) {
                an = ld4(ap0 + k0);
                if (!fpart) an = f4add(f4add(an, ld4(ap1 + k0)), f4add(ld4(ap2 + k0), ld4(ap3 + k0)));
            }
            bn0 = ld4(Bsrc + (size_t)(k0 + brow) * bld + bc4);
            bn1 = ld4(Bsrc + (size_t)(k0 + brow + 16) * bld + bc4);
        }
#pragma unroll
        for (int kk = 0; kk < 32; kk += 8) {
            uint32_t af[4], bf[2][2];
            af[0] = As[cur][wm + g][kk + tg];
            af[1] = As[cur][wm + g + 8][kk + tg];
            af[2] = As[cur][wm + g][kk + tg + 4];
            af[3] = As[cur][wm + g + 8][kk + tg + 4];
#pragma unroll
            for (int j = 0; j < 2; j++) {
                int bc = wn + j * 8 + g;
                bf[j][0] = Bs[cur][kk + tg][bc];
                bf[j][1] = Bs[cur][kk + tg + 4][bc];
            }
            mma_tf32(acc[0], af, bf[0]);
            mma_tf32(acc[1], af, bf[1]);
        }
        if (it < 15) {
            int nxt = cur ^ 1;
            *(uint4*)&As[nxt][arow][acol]     = cvt4(an);
            *(uint4*)&Bs[nxt][brow][bc4]      = cvt4(bn0);
            *(uint4*)&Bs[nxt][brow + 16][bc4] = cvt4(bn1);
            __syncthreads();
            cur = nxt;
        }
    }

#pragma unroll
    for (int j = 0; j < 2; j++) {
        int colin = wn + j * 8 + 2 * tg;
#pragma unroll
        for (int r = 0; r < 2; r++) {
            int mrow = mtile * 32 + wm + g + r * 8;
            if (mrow < Plim) {
                float2 v = make_float2(acc[j][2 * r], acc[j][2 * r + 1]);
                if (fpart)
                    *(float2*)(g_y + (size_t)(t * NPAD + j0f + mrow) * MEMD + n0 + colin) = v;
                else
                    *(float2*)(g_ziou + ((size_t)t * NNODE + j0i + mrow) * NIOU + n0 + colin) = v;
            }
        }
    }
}

// Per-node gate math for one level. One block per (node, tree), 128 thr x 4 dims.
__global__ __launch_bounds__(128) void k_update(
    const int* __restrict__ lch, const int* __restrict__ rch,
    const float* __restrict__ biouh, const float* __restrict__ bfh, int j0)
{
    const int t = blockIdx.y;
    const int j = j0 + blockIdx.x;
    const int* ch = (t ? rch : lch) + j * 4;
    const int c0 = ch[0], c1 = ch[1], c2 = ch[2], c3 = ch[3];
    const int d = threadIdx.x << 2;

    const float* x = g_xiouf + (size_t)(t * NNODE + j) * NCOMB;

    float4 Zi, Zo, Zu;
    if (j >= 384) {  // internal node: ziou was computed by previous level's iou GEMM
        const float* z = g_ziou + ((size_t)t * NNODE + j) * NIOU;
        Zi = ld4(z + d); Zo = ld4(z + 512 + d); Zu = ld4(z + 1024 + d);
    } else {
        Zi = Zo = Zu = make_float4(0.f, 0.f, 0.f, 0.f);
    }

    float4 Y0 = ld4(g_y + (size_t)(t * NPAD + c0) * MEMD + d);
    float4 Y1 = ld4(g_y + (size_t)(t * NPAD + c1) * MEMD + d);
    float4 Y2 = ld4(g_y + (size_t)(t * NPAD + c2) * MEMD + d);
    float4 Y3 = ld4(g_y + (size_t)(t * NPAD + c3) * MEMD + d);
    float4 Cc0 = ld4(g_c + (size_t)(t * NPAD + c0) * MEMD + d);
    float4 Cc1 = ld4(g_c + (size_t)(t * NPAD + c1) * MEMD + d);
    float4 Cc2 = ld4(g_c + (size_t)(t * NPAD + c2) * MEMD + d);
    float4 Cc3 = ld4(g_c + (size_t)(t * NPAD + c3) * MEMD + d);
    float4 Xi = ld4(x + d), Xo = ld4(x + 512 + d), Xu = ld4(x + 1024 + d), Xf = ld4(x + 1536 + d);
    float4 Bi = ld4(biouh + d), Bo = ld4(biouh + 512 + d), Bu = ld4(biouh + 1024 + d), Bf = ld4(bfh + d);

    float4 Oc, Oh;
#define DO(C) { \
    float ig = sigm(Xi.C + Zi.C + Bi.C); \
    float og = sigm(Xo.C + Zo.C + Bo.C); \
    float ug = tanhf(Xu.C + Zu.C + Bu.C); \
    float fb = Xf.C + Bf.C; \
    float c  = ig * ug + sigm(Y0.C + fb) * Cc0.C + sigm(Y1.C + fb) * Cc1.C \
                       + sigm(Y2.C + fb) * Cc2.C + sigm(Y3.C + fb) * Cc3.C; \
    Oc.C = c; Oh.C = og * tanhf(c); }
    DO(x) DO(y) DO(z) DO(w)
#undef DO

    *(float4*)(g_c + (size_t)(t * NPAD + j) * MEMD + d) = Oc;
    *(float4*)(g_h + (size_t)(t * NPAD + j) * MEMD + d) = Oh;
}

// Head part 1: vec = [lc*rc | |lc-rc|] (1024), partial hid pre-acts over d-slices.
__global__ __launch_bounds__(512) void k_head1(const float* __restrict__ Wh)
{
    __shared__ float vec_s[64];
    const int b = blockIdx.x, d0 = b * 64, tid = threadIdx.x;
    const float* lc = g_c + (size_t)(0 * NPAD + (NNODE - 1)) * MEMD;
    const float* rc = g_c + (size_t)(1 * NPAD + (NNODE - 1)) * MEMD;
    if (tid < 64) {
        int dd = d0 + tid;
        vec_s[tid] = (dd < 512) ? lc[dd] * rc[dd] : fabsf(lc[dd - 512] - rc[dd - 512]);
    }
    __syncthreads();
    float acc = 0.f;
#pragma unroll 8
    for (int dd = 0; dd < 64; dd++)
        acc += vec_s[dd] * Wh[(size_t)(d0 + dd) * 512 + tid];
    g_part[b * 512 + tid] = acc;
}

// Head part 2: hid = sigmoid(.+bh); logits = hid@Wp+bp; log_softmax -> out[5]
__global__ __launch_bounds__(512) void k_head2(
    const float* __restrict__ bh, const float* __restrict__ Wp,
    const float* __restrict__ bp, float* __restrict__ out)
{
    __shared__ float hid[512];
    __shared__ float logit[5];
    const int tid = threadIdx.x;
    float a = 0.f;
#pragma unroll
    for (int b = 0; b < 16; b++) a += g_part[b * 512 + tid];
    hid[tid] = sigm(a + bh[tid]);
    __syncthreads();
    if (tid < 160) {
        int c = tid / 32, lane = tid & 31;
        float s = 0.f;
        for (int o = lane; o < 512; o += 32) s += hid[o] * Wp[o * 5 + c];
#pragma unroll
        for (int off = 16; off; off >>= 1) s += __shfl_down_sync(0xffffffffu, s, off);
        if (lane == 0) logit[c] = s + bp[c];
    }
    __syncthreads();
    if (tid == 0) {
        float m = logit[0];
#pragma unroll
        for (int c = 1; c < 5; c++) m = fmaxf(m, logit[c]);
        float se = 0.f;
#pragma unroll
        for (int c = 0; c < 5; c++) se += expf(logit[c] - m);
        float lse = m + logf(se);
#pragma unroll
        for (int c = 0; c < 5; c++) out[c] = logit[c] - lse;
    }
}

extern "C" void kernel_launch(void* const* d_in, const int* in_sizes, int n_in,
                              void* d_out, int out_size)
{
    const int*   linp  = (const int*)d_in[0];
    const int*   rinp  = (const int*)d_in[1];
    const int*   lch   = (const int*)d_in[2];
    const int*   rch   = (const int*)d_in[3];
    const float* emb   = (const float*)d_in[4];
    const float* Wioux = (const float*)d_in[5];
    const float* bioux = (const float*)d_in[6];
    const float* Wiouh = (const float*)d_in[7];
    const float* biouh = (const float*)d_in[8];
    const float* Wfx   = (const float*)d_in[9];
    const float* bfx   = (const float*)d_in[10];
    const float* Wfh   = (const float*)d_in[11];
    const float* bfh   = (const float*)d_in[12];
    const float* Wh    = (const float*)d_in[13];
    const float* bh    = (const float*)d_in[14];
    const float* Wp    = (const float*)d_in[15];
    const float* bp    = (const float*)d_in[16];
    float* out = (float*)d_out;

    k_zero<<<1, 512>>>();
    // Precompute x-projections for both trees (M=1024 rows, 32-row tiles).
    k_pre<<<dim3(32, 32, 1), 256>>>(emb, linp, rinp, Wioux, Wfx, bioux, bfx);

    // Complete 4-ary tree levels in scan order (j-space, deepest first).
    static const int j0s[6]  = {0, 171, 427, 491, 507, 511};
    static const int cnt[6]  = {171, 256, 64, 16, 4, 1};
    static const int j0i[5]  = {384, 427, 491, 507, 511};  // internal rows of next level
    static const int cnti[5] = {43, 64, 16, 4, 1};
    for (int l = 0; l < 6; l++) {
        k_update<<<dim3(cnt[l], 2), 128>>>(lch, rch, biouh, bfh, j0s[l]);
        if (l < 5) {
            int mtf = (cnt[l] + 31) / 32;
            int mti = (cnti[l] + 31) / 32;
            k_lvl<<<dim3(8 * mtf + 24 * mti, 1, 2), 256>>>(
                lch, rch, Wiouh, Wfh, j0s[l], cnt[l], j0i[l], cnti[l], mtf);
        }
    }
    k_head1<<<16, 512>>>(Wh);
    k_head2<<<1, 512>>>(bh, Wp, bp, out);
}